// round 13
// baseline (speedup 1.0000x reference)
#include <cuda_runtime.h>
#include <cuda_fp16.h>

#define HEADS 4
#define DIM 64
#define NEG_SLOPE 0.2f
#define NODES_MAX 100000
#define EDGES_MAX 1000000

// ---- scratch (static __device__; no allocation) ----
__device__ __half2 g_h[NODES_MAX * 32];      // 12.8 MB, L2-resident (fp16)
__device__ float4 g_asrc[NODES_MAX];
__device__ float4 g_adst[NODES_MAX];
__device__ int    g_counts[NODES_MAX];
__device__ int    g_offsets[NODES_MAX + 1];
__device__ int    g_rank[EDGES_MAX];
__device__ int    g_scan_tot[128];
__device__ int    g_scan_flag[128];
__device__ int    g_scan_fin;
__device__ int    g_srcs[EDGES_MAX];
__device__ int    g_is64;

__device__ __forceinline__ void ffma2(unsigned long long& d, unsigned long long a,
                                      unsigned long long b) {
    asm("fma.rn.f32x2 %0, %1, %2, %0;" : "+l"(d) : "l"(a), "l"(b));
}

__device__ __forceinline__ int clampi(long long v, int n) {
    int x = (int)v;
    return x < 0 ? 0 : (x >= n ? n - 1 : x);
}

// ---------------------------------------------------------------------------
// zero counts + scan flags/fin + sentinel + dtype detect (proven R9 form)
__global__ void k_zero_detect(const unsigned* __restrict__ ei, int n, int e) {
    int i = blockIdx.x * blockDim.x + threadIdx.x;
    if (i < n) g_counts[i] = 0;
    if (i < 128) g_scan_flag[i] = 0;
    if (i == 0) { g_offsets[n] = e; g_scan_fin = 0; }
    if (blockIdx.x == 0 && threadIdx.x < 32) {
        unsigned lane = threadIdx.x;
        unsigned v1 = ei[2u * lane + 1u];
        unsigned v2 = ei[2u * (lane + 32u) + 1u];
        int nz = (v1 != 0u) || (v2 != 0u);
        unsigned any = __ballot_sync(0xffffffffu, nz);
        if (lane == 0) g_is64 = (any == 0u) ? 1 : 0;
    }
}

// ---------------------------------------------------------------------------
// h = x @ W + attention scalars (side stream, forked at t=0).
__global__ void __launch_bounds__(256) k_gemm(
        const float* __restrict__ x, const float* __restrict__ W,
        const float* __restrict__ att_s, const float* __restrict__ att_d, int n) {
    __shared__ unsigned long long sx[8][4 * 64];
    int tid = threadIdx.x, lane = tid & 31, wid = tid >> 5;
    int rowBase = (blockIdx.x * 8 + wid) * 32;

    unsigned long long Wr[64];
    #pragma unroll
    for (int k = 0; k < 64; k++)
        Wr[k] = *(const unsigned long long*)(W + k * 64 + lane * 2);
    float2 asw = *(const float2*)(att_s + lane * 2);
    float2 adw = *(const float2*)(att_d + lane * 2);

    unsigned FULL = 0xffffffffu;
    int hdsel = lane >> 3;

    for (int r4 = 0; r4 < 32; r4 += 4) {
        int row0 = rowBase + r4;

        #pragma unroll
        for (int it = 0; it < 4; it++) {
            int g2 = it * 32 + lane;
            int r = g2 >> 5;
            float2 v = make_float2(0.f, 0.f);
            if (row0 + r < n) v = ((const float2*)x)[row0 * 32 + g2];
            sx[wid][g2 * 2]     = ((unsigned long long)__float_as_uint(v.x) << 32) |
                                   (unsigned long long)__float_as_uint(v.x);
            sx[wid][g2 * 2 + 1] = ((unsigned long long)__float_as_uint(v.y) << 32) |
                                   (unsigned long long)__float_as_uint(v.y);
        }
        __syncwarp();

        unsigned long long a0 = 0ull, a1 = 0ull, a2 = 0ull, a3 = 0ull;
        const unsigned long long* xr = &sx[wid][0];
        #pragma unroll
        for (int k = 0; k < 64; k++) {
            ffma2(a0, xr[k],       Wr[k]);
            ffma2(a1, xr[64 + k],  Wr[k]);
            ffma2(a2, xr[128 + k], Wr[k]);
            ffma2(a3, xr[192 + k], Wr[k]);
        }
        __syncwarp();

        unsigned long long accs[4] = {a0, a1, a2, a3};
        #pragma unroll
        for (int r = 0; r < 4; r++) {
            int row = row0 + r;
            float c0 = __uint_as_float((unsigned)(accs[r] & 0xffffffffull));
            float c1 = __uint_as_float((unsigned)(accs[r] >> 32));
            if (row < n)
                g_h[row * 32 + lane] = __floats2half2_rn(c0, c1);
            float ts = c0 * asw.x + c1 * asw.y;
            float td = c0 * adw.x + c1 * adw.y;
            #pragma unroll
            for (int m = 1; m < 8; m <<= 1) {
                ts += __shfl_xor_sync(FULL, ts, m);
                td += __shfl_xor_sync(FULL, td, m);
            }
            if (row < n && (lane & 7) == 0) {
                ((float*)g_asrc)[row * 4 + hdsel] = ts;
                ((float*)g_adst)[row * 4 + hdsel] = td;
            }
        }
    }
}

// ---------------------------------------------------------------------------
// in-degree histogram; atomic return = rank in dst segment (proven R9 form).
__global__ void k_count(const void* __restrict__ ei, int e, int n) {
    int i0 = (blockIdx.x * blockDim.x + threadIdx.x) * 2;
    if (i0 >= e) return;
    int is64 = g_is64;
    if (i0 + 2 <= e) {
        int d0, d1;
        if (is64) {
            longlong2 d = *(const longlong2*)((const long long*)ei + e + i0);
            d0 = clampi(d.x, n); d1 = clampi(d.y, n);
        } else {
            int2 d = *(const int2*)((const int*)ei + e + i0);
            d0 = clampi(d.x, n); d1 = clampi(d.y, n);
        }
        int r0 = atomicAdd(&g_counts[d0], 1);
        int r1 = atomicAdd(&g_counts[d1], 1);
        *(int2*)(g_rank + i0) = make_int2(r0, r1);
    } else {
        long long d = is64 ? ((const long long*)ei)[e + i0]
                           : (long long)((const int*)ei)[e + i0];
        g_rank[i0] = atomicAdd(&g_counts[clampi(d, n)], 1);
    }
}

// ---------------------------------------------------------------------------
// FUSED scan + scatter.
// Blocks 0..nsb-1 (nsb=98): decoupled-lookback exclusive scan (predecessor-only
// flags) over counts -> offsets, then signal via g_scan_fin.
// ALL blocks: spin until scan complete, then atomic-free scatter.
// Safety: blocks dispatch in bid order; blocks 0..97 are inside wave 1
// (>=148 resident, 1/SM min) -> scan always completes -> spinners released.
__global__ void __launch_bounds__(256) k_scansc(const void* __restrict__ ei,
                                                int e, int n, int nsb) {
    int t = threadIdx.x, b = blockIdx.x;
    unsigned FULL = 0xffffffffu;

    if (b < nsb) {
        __shared__ int wtot[8];
        __shared__ int s_pref;
        int lane = t & 31, wid = t >> 5;
        int base = (b * 256 + t) * 4;
        int4 v = make_int4(0, 0, 0, 0);
        if (base + 4 <= n) v = *(const int4*)(g_counts + base);
        else {
            if (base < n)     v.x = g_counts[base];
            if (base + 1 < n) v.y = g_counts[base + 1];
            if (base + 2 < n) v.z = g_counts[base + 2];
        }
        int local = v.x + v.y + v.z + v.w;

        int ws = local;
        #pragma unroll
        for (int o = 1; o < 32; o <<= 1) {
            int u = __shfl_up_sync(FULL, ws, o);
            if (lane >= o) ws += u;
        }
        if (lane == 31) wtot[wid] = ws;
        __syncthreads();

        if (t < 32) {
            int w = (t < 8) ? wtot[t] : 0;
            #pragma unroll
            for (int o = 1; o < 8; o <<= 1) {
                int u = __shfl_up_sync(FULL, w, o);
                if (t >= o) w += u;
            }
            if (t < 8) wtot[t] = w;
            int btot = __shfl_sync(FULL, w, 7);
            if (t == 0) {
                g_scan_tot[b] = btot;
                __threadfence();
                atomicExch(&g_scan_flag[b], 1);
            }
            int acc = 0;
            for (int i = t; i < b; i += 32) {
                while (((volatile int*)g_scan_flag)[i] == 0) { }
                acc += ((volatile int*)g_scan_tot)[i];
            }
            #pragma unroll
            for (int o = 16; o; o >>= 1) acc += __shfl_xor_sync(FULL, acc, o);
            if (t == 0) s_pref = acc;
        }
        __syncthreads();

        int blkpre = wid ? wtot[wid - 1] : 0;
        int pref = s_pref + blkpre + ws - local;   // exclusive prefix
        int o0 = pref, o1 = o0 + v.x, o2 = o1 + v.y, o3 = o2 + v.z;
        if (base + 4 <= n) {
            *(int4*)(g_offsets + base) = make_int4(o0, o1, o2, o3);
        } else {
            int ov[4] = {o0, o1, o2, o3};
            for (int i = 0; base + i < n && i < 4; i++)
                g_offsets[base + i] = ov[i];
        }
        __threadfence();          // publish this thread's offset writes
        __syncthreads();
        if (t == 0) atomicAdd(&g_scan_fin, 1);
    }

    // all blocks: wait for the full scan
    if (t == 0) {
        while (*(volatile int*)&g_scan_fin < nsb) { __nanosleep(64); }
    }
    __syncthreads();

    // scatter: pos = offsets[dst] + precomputed rank
    int i0 = (b * 256 + t) * 2;
    if (i0 >= e) return;
    int is64 = g_is64;
    if (i0 + 2 <= e) {
        int s0, s1, d0, d1;
        if (is64) {
            longlong2 s = *(const longlong2*)((const long long*)ei + i0);
            longlong2 d = *(const longlong2*)((const long long*)ei + e + i0);
            s0 = clampi(s.x, n); s1 = clampi(s.y, n);
            d0 = clampi(d.x, n); d1 = clampi(d.y, n);
        } else {
            int2 s = *(const int2*)((const int*)ei + i0);
            int2 d = *(const int2*)((const int*)ei + e + i0);
            s0 = clampi(s.x, n); s1 = clampi(s.y, n);
            d0 = clampi(d.x, n); d1 = clampi(d.y, n);
        }
        int2 rk = *(const int2*)(g_rank + i0);
        int p0 = g_offsets[d0] + rk.x;
        int p1 = g_offsets[d1] + rk.y;
        g_srcs[p0] = s0;
        g_srcs[p1] = s1;
    } else {
        long long sl = is64 ? ((const long long*)ei)[i0]
                            : (long long)((const int*)ei)[i0];
        long long dl = is64 ? ((const long long*)ei)[e + i0]
                            : (long long)((const int*)ei)[e + i0];
        int pos = g_offsets[clampi(dl, n)] + g_rank[i0];
        g_srcs[pos] = clampi(sl, n);
    }
}

// ---------------------------------------------------------------------------
// 4 nodes per warp (8-lane groups). Lane owns 8 channels (LDG.128 fp16).
__global__ void __launch_bounds__(256) k_node(
        const float* __restrict__ bias, const float* __restrict__ gamma,
        const float* __restrict__ beta, float* __restrict__ out, int n) {
    __shared__ float s_ex[8][4][8][4];
    __shared__ int   s_src[8][4][8];
    int wslot = threadIdx.x >> 5, lane = threadIdx.x & 31;
    int grp = lane >> 3, gl = lane & 7;
    int node = (blockIdx.x * 8 + wslot) * 4 + grp;
    bool valid = node < n;
    unsigned FULL = 0xffffffffu;

    int beg = 0, deg = 0;
    float4 ad = make_float4(0.f, 0.f, 0.f, 0.f);
    if (valid) {
        beg = g_offsets[node];
        deg = g_offsets[node + 1] - beg;
        ad = g_adst[node];
    }
    int hd = gl >> 1;

    float s0 = 0.f, s1 = 0.f, s2 = 0.f, s3 = 0.f;
    float a0 = 0.f, a1 = 0.f, a2 = 0.f, a3 = 0.f;
    float a4 = 0.f, a5 = 0.f, a6 = 0.f, a7 = 0.f;

    const uint4* hb = (const uint4*)g_h;

    int nch = (deg + 7) >> 3;
    #pragma unroll
    for (int o = 16; o; o >>= 1) nch = max(nch, __shfl_xor_sync(FULL, nch, o));

    for (int c = 0; c < nch; c++) {
        int i = c * 8 + gl;
        float4 ex4 = make_float4(0.f, 0.f, 0.f, 0.f);
        int sv = 0;
        if (i < deg) {
            sv = g_srcs[beg + i];
            float4 as = g_asrc[sv];
            float e0 = as.x + ad.x; e0 = e0 >= 0.f ? e0 : NEG_SLOPE * e0;
            float e1 = as.y + ad.y; e1 = e1 >= 0.f ? e1 : NEG_SLOPE * e1;
            float e2 = as.z + ad.z; e2 = e2 >= 0.f ? e2 : NEG_SLOPE * e2;
            float e3 = as.w + ad.w; e3 = e3 >= 0.f ? e3 : NEG_SLOPE * e3;
            ex4.x = __expf(e0); ex4.y = __expf(e1);
            ex4.z = __expf(e2); ex4.w = __expf(e3);
            s0 += ex4.x; s1 += ex4.y; s2 += ex4.z; s3 += ex4.w;
        }
        s_src[wslot][grp][gl] = sv;
        *(float4*)&s_ex[wslot][grp][gl][0] = ex4;
        __syncwarp();
        int cnt = min(8, deg - c * 8);
        if (cnt == 8) {
            #pragma unroll
            for (int j = 0; j < 8; j++) {
                int   ss = s_src[wslot][grp][j];
                float al = s_ex[wslot][grp][j][hd];
                uint4 hv = hb[ss * 8 + gl];
                float2 p0 = __half22float2(*(__half2*)&hv.x);
                float2 p1 = __half22float2(*(__half2*)&hv.y);
                float2 p2 = __half22float2(*(__half2*)&hv.z);
                float2 p3 = __half22float2(*(__half2*)&hv.w);
                a0 = fmaf(al, p0.x, a0); a1 = fmaf(al, p0.y, a1);
                a2 = fmaf(al, p1.x, a2); a3 = fmaf(al, p1.y, a3);
                a4 = fmaf(al, p2.x, a4); a5 = fmaf(al, p2.y, a5);
                a6 = fmaf(al, p3.x, a6); a7 = fmaf(al, p3.y, a7);
            }
        } else {
            for (int j = 0; j < cnt; j++) {
                int   ss = s_src[wslot][grp][j];
                float al = s_ex[wslot][grp][j][hd];
                uint4 hv = hb[ss * 8 + gl];
                float2 p0 = __half22float2(*(__half2*)&hv.x);
                float2 p1 = __half22float2(*(__half2*)&hv.y);
                float2 p2 = __half22float2(*(__half2*)&hv.z);
                float2 p3 = __half22float2(*(__half2*)&hv.w);
                a0 = fmaf(al, p0.x, a0); a1 = fmaf(al, p0.y, a1);
                a2 = fmaf(al, p1.x, a2); a3 = fmaf(al, p1.y, a3);
                a4 = fmaf(al, p2.x, a4); a5 = fmaf(al, p2.y, a5);
                a6 = fmaf(al, p3.x, a6); a7 = fmaf(al, p3.y, a7);
            }
        }
        __syncwarp();
    }

    #pragma unroll
    for (int o = 4; o; o >>= 1) {
        s0 += __shfl_xor_sync(FULL, s0, o);
        s1 += __shfl_xor_sync(FULL, s1, o);
        s2 += __shfl_xor_sync(FULL, s2, o);
        s3 += __shfl_xor_sync(FULL, s3, o);
    }
    float s   = (hd == 0) ? s0 : (hd == 1) ? s1 : (hd == 2) ? s2 : s3;
    float inv = 1.f / (s + 1e-16f);

    float4 bi0 = *(const float4*)(bias + gl * 8);
    float4 bi1 = *(const float4*)(bias + gl * 8 + 4);
    float o0 = a0 * inv + bi0.x, o1 = a1 * inv + bi0.y;
    float o2 = a2 * inv + bi0.z, o3 = a3 * inv + bi0.w;
    float o4 = a4 * inv + bi1.x, o5 = a5 * inv + bi1.y;
    float o6 = a6 * inv + bi1.z, o7 = a7 * inv + bi1.w;

    float ssum = o0 + o1 + o2 + o3 + o4 + o5 + o6 + o7;
    float ssq  = o0*o0 + o1*o1 + o2*o2 + o3*o3 + o4*o4 + o5*o5 + o6*o6 + o7*o7;
    #pragma unroll
    for (int o = 4; o; o >>= 1) {
        ssum += __shfl_xor_sync(FULL, ssum, o);
        ssq  += __shfl_xor_sync(FULL, ssq, o);
    }
    float mu  = ssum * (1.f / 64.f);
    float var = ssq * (1.f / 64.f) - mu * mu;
    float r   = rsqrtf(var + 1e-5f);

    if (valid) {
        float4 ga0 = *(const float4*)(gamma + gl * 8);
        float4 ga1 = *(const float4*)(gamma + gl * 8 + 4);
        float4 be0 = *(const float4*)(beta + gl * 8);
        float4 be1 = *(const float4*)(beta + gl * 8 + 4);
        float4 r0, r1;
        r0.x = (o0 - mu) * r * ga0.x + be0.x;
        r0.y = (o1 - mu) * r * ga0.y + be0.y;
        r0.z = (o2 - mu) * r * ga0.z + be0.z;
        r0.w = (o3 - mu) * r * ga0.w + be0.w;
        r1.x = (o4 - mu) * r * ga1.x + be1.x;
        r1.y = (o5 - mu) * r * ga1.y + be1.y;
        r1.z = (o6 - mu) * r * ga1.z + be1.z;
        r1.w = (o7 - mu) * r * ga1.w + be1.w;
        float4* op = (float4*)(out + node * 64 + gl * 8);
        op[0] = r0;
        op[1] = r1;
    }
}

// ---------------------------------------------------------------------------
extern "C" void kernel_launch(void* const* d_in, const int* in_sizes, int n_in,
                              void* d_out, int out_size) {
    const float* x     = (const float*)d_in[0];
    const void*  ei    = d_in[1];
    const float* W     = (const float*)d_in[2];
    const float* att_s = (const float*)d_in[3];
    const float* att_d = (const float*)d_in[4];
    const float* bias  = (const float*)d_in[5];
    const float* gamma = (const float*)d_in[6];
    const float* beta  = (const float*)d_in[7];
    float* out = (float*)d_out;

    int n = in_sizes[0] / DIM;    // 100000
    int e = in_sizes[1] / 2;      // 1000000
    int nsb = (n + 1023) / 1024;  // 98 scan blocks (<=128)

    // one-time resource init (streams/events; no device memory)
    static cudaStream_t s2 = 0;
    static cudaEvent_t evF = 0, evJ = 0;
    if (s2 == 0) {
        cudaStreamCreateWithFlags(&s2, cudaStreamNonBlocking);
        cudaEventCreateWithFlags(&evF, cudaEventDisableTiming);
        cudaEventCreateWithFlags(&evJ, cudaEventDisableTiming);
    }

    // fork gemm at t=0 (no dependencies); edge pipeline on main stream.
    cudaEventRecord(evF, 0);
    cudaStreamWaitEvent(s2, evF, 0);
    k_gemm<<<(n + 255) / 256, 256, 0, s2>>>(x, W, att_s, att_d, n);
    cudaEventRecord(evJ, s2);

    k_zero_detect<<<(n + 255) / 256, 256>>>((const unsigned*)ei, n, e);
    k_count<<<(e / 2 + 255) / 256, 256>>>(ei, e, n);
    k_scansc<<<(e / 2 + 255) / 256, 256>>>(ei, e, n, nsb);

    cudaStreamWaitEvent(0, evJ, 0);
    k_node<<<(n + 31) / 32, 256>>>(bias, gamma, beta, out, n);
}

// round 14
// speedup vs baseline: 1.0367x; 1.0367x over previous
#include <cuda_runtime.h>
#include <cuda_fp16.h>

#define HEADS 4
#define DIM 64
#define NEG_SLOPE 0.2f
#define NODES_MAX 100000
#define EDGES_MAX 1000000

// ---- scratch (static __device__; no allocation) ----
__device__ __half2 g_h[NODES_MAX * 32];      // 12.8 MB, L2-resident (fp16)
__device__ float4 g_asrc[NODES_MAX];
__device__ float4 g_adst[NODES_MAX];
__device__ int    g_counts[NODES_MAX];
__device__ int    g_offsets[NODES_MAX + 1];
__device__ int    g_rank[EDGES_MAX];         // edge's rank within its dst segment
__device__ int    g_scan_tot[128];
__device__ int    g_scan_flag[128];
__device__ int    g_srcs[EDGES_MAX];
__device__ int    g_is64;

__device__ __forceinline__ void ffma2(unsigned long long& d, unsigned long long a,
                                      unsigned long long b) {
    asm("fma.rn.f32x2 %0, %1, %2, %0;" : "+l"(d) : "l"(a), "l"(b));
}

__device__ __forceinline__ int clampi(long long v, int n) {
    int x = (int)v;
    return x < 0 ? 0 : (x >= n ? n - 1 : x);
}

// ---------------------------------------------------------------------------
// zero counts + scan flags + sentinel offset + detect edge_index dtype
__global__ void k_zero_detect(const unsigned* __restrict__ ei, int n, int e) {
    int i = blockIdx.x * blockDim.x + threadIdx.x;
    if (i < n) g_counts[i] = 0;
    if (i < 128) g_scan_flag[i] = 0;
    if (i == 0) g_offsets[n] = e;
    if (blockIdx.x == 0 && threadIdx.x < 32) {
        unsigned lane = threadIdx.x;
        unsigned v1 = ei[2u * lane + 1u];
        unsigned v2 = ei[2u * (lane + 32u) + 1u];
        int nz = (v1 != 0u) || (v2 != 0u);
        unsigned any = __ballot_sync(0xffffffffu, nz);
        if (lane == 0) g_is64 = (any == 0u) ? 1 : 0;
    }
}

// ---------------------------------------------------------------------------
// h = x @ W + attention scalars (side stream, overlapped with edge pipeline).
__global__ void __launch_bounds__(256) k_gemm(
        const float* __restrict__ x, const float* __restrict__ W,
        const float* __restrict__ att_s, const float* __restrict__ att_d, int n) {
    __shared__ unsigned long long sx[8][4 * 64];
    int tid = threadIdx.x, lane = tid & 31, wid = tid >> 5;
    int rowBase = (blockIdx.x * 8 + wid) * 32;

    unsigned long long Wr[64];
    #pragma unroll
    for (int k = 0; k < 64; k++)
        Wr[k] = *(const unsigned long long*)(W + k * 64 + lane * 2);
    float2 asw = *(const float2*)(att_s + lane * 2);
    float2 adw = *(const float2*)(att_d + lane * 2);

    unsigned FULL = 0xffffffffu;
    int hdsel = lane >> 3;

    for (int r4 = 0; r4 < 32; r4 += 4) {
        int row0 = rowBase + r4;

        #pragma unroll
        for (int it = 0; it < 4; it++) {
            int g2 = it * 32 + lane;
            int r = g2 >> 5;
            float2 v = make_float2(0.f, 0.f);
            if (row0 + r < n) v = ((const float2*)x)[row0 * 32 + g2];
            sx[wid][g2 * 2]     = ((unsigned long long)__float_as_uint(v.x) << 32) |
                                   (unsigned long long)__float_as_uint(v.x);
            sx[wid][g2 * 2 + 1] = ((unsigned long long)__float_as_uint(v.y) << 32) |
                                   (unsigned long long)__float_as_uint(v.y);
        }
        __syncwarp();

        unsigned long long a0 = 0ull, a1 = 0ull, a2 = 0ull, a3 = 0ull;
        const unsigned long long* xr = &sx[wid][0];
        #pragma unroll
        for (int k = 0; k < 64; k++) {
            ffma2(a0, xr[k],       Wr[k]);
            ffma2(a1, xr[64 + k],  Wr[k]);
            ffma2(a2, xr[128 + k], Wr[k]);
            ffma2(a3, xr[192 + k], Wr[k]);
        }
        __syncwarp();

        unsigned long long accs[4] = {a0, a1, a2, a3};
        #pragma unroll
        for (int r = 0; r < 4; r++) {
            int row = row0 + r;
            float c0 = __uint_as_float((unsigned)(accs[r] & 0xffffffffull));
            float c1 = __uint_as_float((unsigned)(accs[r] >> 32));
            if (row < n)
                g_h[row * 32 + lane] = __floats2half2_rn(c0, c1);
            float ts = c0 * asw.x + c1 * asw.y;
            float td = c0 * adw.x + c1 * adw.y;
            #pragma unroll
            for (int m = 1; m < 8; m <<= 1) {
                ts += __shfl_xor_sync(FULL, ts, m);
                td += __shfl_xor_sync(FULL, td, m);
            }
            if (row < n && (lane & 7) == 0) {
                ((float*)g_asrc)[row * 4 + hdsel] = ts;
                ((float*)g_adst)[row * 4 + hdsel] = td;
            }
        }
    }
}

// ---------------------------------------------------------------------------
// in-degree histogram; atomic return value = edge rank in its dst segment.
__global__ void k_count(const void* __restrict__ ei, int e, int n) {
    int i0 = (blockIdx.x * blockDim.x + threadIdx.x) * 2;
    if (i0 >= e) return;
    int is64 = g_is64;
    if (i0 + 2 <= e) {
        int d0, d1;
        if (is64) {
            longlong2 d = *(const longlong2*)((const long long*)ei + e + i0);
            d0 = clampi(d.x, n); d1 = clampi(d.y, n);
        } else {
            int2 d = *(const int2*)((const int*)ei + e + i0);
            d0 = clampi(d.x, n); d1 = clampi(d.y, n);
        }
        int r0 = atomicAdd(&g_counts[d0], 1);
        int r1 = atomicAdd(&g_counts[d1], 1);
        *(int2*)(g_rank + i0) = make_int2(r0, r1);
    } else {
        long long d = is64 ? ((const long long*)ei)[e + i0]
                           : (long long)((const int*)ei)[e + i0];
        g_rank[i0] = atomicAdd(&g_counts[clampi(d, n)], 1);
    }
}

// ---------------------------------------------------------------------------
// exclusive scan: 98 blocks x 256 threads x 4 elems; warp-shuffle scan
// (2 block barriers) + decoupled predecessor-only lookback (concurrency-safe).
__global__ void __launch_bounds__(256) k_scan(int n) {
    __shared__ int wtot[8];
    __shared__ int s_pref;
    int t = threadIdx.x, b = blockIdx.x;
    int lane = t & 31, wid = t >> 5;
    unsigned FULL = 0xffffffffu;

    int base = (b * 256 + t) * 4;
    int4 v = make_int4(0, 0, 0, 0);
    if (base + 4 <= n) v = *(const int4*)(g_counts + base);
    else {
        if (base < n)     v.x = g_counts[base];
        if (base + 1 < n) v.y = g_counts[base + 1];
        if (base + 2 < n) v.z = g_counts[base + 2];
    }
    int local = v.x + v.y + v.z + v.w;

    // warp inclusive scan
    int ws = local;
    #pragma unroll
    for (int o = 1; o < 32; o <<= 1) {
        int u = __shfl_up_sync(FULL, ws, o);
        if (lane >= o) ws += u;
    }
    if (lane == 31) wtot[wid] = ws;
    __syncthreads();

    if (t < 32) {
        int w = (t < 8) ? wtot[t] : 0;
        #pragma unroll
        for (int o = 1; o < 8; o <<= 1) {
            int u = __shfl_up_sync(FULL, w, o);
            if (t >= o) w += u;
        }
        if (t < 8) wtot[t] = w;
        int btot = __shfl_sync(FULL, w, 7);
        if (t == 0) {
            g_scan_tot[b] = btot;
            __threadfence();
            atomicExch(&g_scan_flag[b], 1);
        }
        // predecessor-only lookback
        int acc = 0;
        for (int i = t; i < b; i += 32) {
            while (((volatile int*)g_scan_flag)[i] == 0) { }
            acc += ((volatile int*)g_scan_tot)[i];
        }
        #pragma unroll
        for (int o = 16; o; o >>= 1) acc += __shfl_xor_sync(FULL, acc, o);
        if (t == 0) s_pref = acc;
    }
    __syncthreads();

    int blkpre = wid ? wtot[wid - 1] : 0;
    int pref = s_pref + blkpre + ws - local;   // exclusive prefix
    int o0 = pref, o1 = o0 + v.x, o2 = o1 + v.y, o3 = o2 + v.z;
    if (base + 4 <= n) {
        *(int4*)(g_offsets + base) = make_int4(o0, o1, o2, o3);
    } else {
        int ov[4] = {o0, o1, o2, o3};
        for (int i = 0; base + i < n && i < 4; i++)
            g_offsets[base + i] = ov[i];
    }
}

// ---------------------------------------------------------------------------
// atomic-free scatter: pos = offsets[dst] + precomputed rank.
__global__ void k_scatter(const void* __restrict__ ei, int e, int n) {
    int i0 = (blockIdx.x * blockDim.x + threadIdx.x) * 2;
    if (i0 >= e) return;
    int is64 = g_is64;
    if (i0 + 2 <= e) {
        int s0, s1, d0, d1;
        if (is64) {
            longlong2 s = *(const longlong2*)((const long long*)ei + i0);
            longlong2 d = *(const longlong2*)((const long long*)ei + e + i0);
            s0 = clampi(s.x, n); s1 = clampi(s.y, n);
            d0 = clampi(d.x, n); d1 = clampi(d.y, n);
        } else {
            int2 s = *(const int2*)((const int*)ei + i0);
            int2 d = *(const int2*)((const int*)ei + e + i0);
            s0 = clampi(s.x, n); s1 = clampi(s.y, n);
            d0 = clampi(d.x, n); d1 = clampi(d.y, n);
        }
        int2 rk = *(const int2*)(g_rank + i0);
        int p0 = g_offsets[d0] + rk.x;
        int p1 = g_offsets[d1] + rk.y;
        g_srcs[p0] = s0;
        g_srcs[p1] = s1;
    } else {
        long long sl = is64 ? ((const long long*)ei)[i0]
                            : (long long)((const int*)ei)[i0];
        long long dl = is64 ? ((const long long*)ei)[e + i0]
                            : (long long)((const int*)ei)[e + i0];
        int pos = g_offsets[clampi(dl, n)] + g_rank[i0];
        g_srcs[pos] = clampi(sl, n);
    }
}

// ---------------------------------------------------------------------------
// 4 nodes per warp (8-lane groups). Lane owns 8 channels (LDG.128 fp16).
__global__ void __launch_bounds__(256) k_node(
        const float* __restrict__ bias, const float* __restrict__ gamma,
        const float* __restrict__ beta, float* __restrict__ out, int n) {
    __shared__ float s_ex[8][4][8][4];
    __shared__ int   s_src[8][4][8];
    int wslot = threadIdx.x >> 5, lane = threadIdx.x & 31;
    int grp = lane >> 3, gl = lane & 7;
    int node = (blockIdx.x * 8 + wslot) * 4 + grp;
    bool valid = node < n;
    unsigned FULL = 0xffffffffu;

    int beg = 0, deg = 0;
    float4 ad = make_float4(0.f, 0.f, 0.f, 0.f);
    if (valid) {
        beg = g_offsets[node];
        deg = g_offsets[node + 1] - beg;
        ad = g_adst[node];
    }
    int hd = gl >> 1;

    float s0 = 0.f, s1 = 0.f, s2 = 0.f, s3 = 0.f;
    float a0 = 0.f, a1 = 0.f, a2 = 0.f, a3 = 0.f;
    float a4 = 0.f, a5 = 0.f, a6 = 0.f, a7 = 0.f;

    const uint4* hb = (const uint4*)g_h;

    int nch = (deg + 7) >> 3;
    #pragma unroll
    for (int o = 16; o; o >>= 1) nch = max(nch, __shfl_xor_sync(FULL, nch, o));

    for (int c = 0; c < nch; c++) {
        int i = c * 8 + gl;
        float4 ex4 = make_float4(0.f, 0.f, 0.f, 0.f);
        int sv = 0;
        if (i < deg) {
            sv = g_srcs[beg + i];
            float4 as = g_asrc[sv];
            float e0 = as.x + ad.x; e0 = e0 >= 0.f ? e0 : NEG_SLOPE * e0;
            float e1 = as.y + ad.y; e1 = e1 >= 0.f ? e1 : NEG_SLOPE * e1;
            float e2 = as.z + ad.z; e2 = e2 >= 0.f ? e2 : NEG_SLOPE * e2;
            float e3 = as.w + ad.w; e3 = e3 >= 0.f ? e3 : NEG_SLOPE * e3;
            ex4.x = __expf(e0); ex4.y = __expf(e1);
            ex4.z = __expf(e2); ex4.w = __expf(e3);
            s0 += ex4.x; s1 += ex4.y; s2 += ex4.z; s3 += ex4.w;
        }
        s_src[wslot][grp][gl] = sv;
        *(float4*)&s_ex[wslot][grp][gl][0] = ex4;
        __syncwarp();
        int cnt = min(8, deg - c * 8);
        for (int j = 0; j < cnt; j++) {
            int   ss = s_src[wslot][grp][j];
            float al = s_ex[wslot][grp][j][hd];
            uint4 hv = hb[ss * 8 + gl];
            float2 p0 = __half22float2(*(__half2*)&hv.x);
            float2 p1 = __half22float2(*(__half2*)&hv.y);
            float2 p2 = __half22float2(*(__half2*)&hv.z);
            float2 p3 = __half22float2(*(__half2*)&hv.w);
            a0 = fmaf(al, p0.x, a0); a1 = fmaf(al, p0.y, a1);
            a2 = fmaf(al, p1.x, a2); a3 = fmaf(al, p1.y, a3);
            a4 = fmaf(al, p2.x, a4); a5 = fmaf(al, p2.y, a5);
            a6 = fmaf(al, p3.x, a6); a7 = fmaf(al, p3.y, a7);
        }
        __syncwarp();
    }

    #pragma unroll
    for (int o = 4; o; o >>= 1) {
        s0 += __shfl_xor_sync(FULL, s0, o);
        s1 += __shfl_xor_sync(FULL, s1, o);
        s2 += __shfl_xor_sync(FULL, s2, o);
        s3 += __shfl_xor_sync(FULL, s3, o);
    }
    float s   = (hd == 0) ? s0 : (hd == 1) ? s1 : (hd == 2) ? s2 : s3;
    float inv = 1.f / (s + 1e-16f);

    float4 bi0 = *(const float4*)(bias + gl * 8);
    float4 bi1 = *(const float4*)(bias + gl * 8 + 4);
    float o0 = a0 * inv + bi0.x, o1 = a1 * inv + bi0.y;
    float o2 = a2 * inv + bi0.z, o3 = a3 * inv + bi0.w;
    float o4 = a4 * inv + bi1.x, o5 = a5 * inv + bi1.y;
    float o6 = a6 * inv + bi1.z, o7 = a7 * inv + bi1.w;

    float ssum = o0 + o1 + o2 + o3 + o4 + o5 + o6 + o7;
    float ssq  = o0*o0 + o1*o1 + o2*o2 + o3*o3 + o4*o4 + o5*o5 + o6*o6 + o7*o7;
    #pragma unroll
    for (int o = 4; o; o >>= 1) {
        ssum += __shfl_xor_sync(FULL, ssum, o);
        ssq  += __shfl_xor_sync(FULL, ssq, o);
    }
    float mu  = ssum * (1.f / 64.f);
    float var = ssq * (1.f / 64.f) - mu * mu;
    float r   = rsqrtf(var + 1e-5f);

    if (valid) {
        float4 ga0 = *(const float4*)(gamma + gl * 8);
        float4 ga1 = *(const float4*)(gamma + gl * 8 + 4);
        float4 be0 = *(const float4*)(beta + gl * 8);
        float4 be1 = *(const float4*)(beta + gl * 8 + 4);
        float4 r0, r1;
        r0.x = (o0 - mu) * r * ga0.x + be0.x;
        r0.y = (o1 - mu) * r * ga0.y + be0.y;
        r0.z = (o2 - mu) * r * ga0.z + be0.z;
        r0.w = (o3 - mu) * r * ga0.w + be0.w;
        r1.x = (o4 - mu) * r * ga1.x + be1.x;
        r1.y = (o5 - mu) * r * ga1.y + be1.y;
        r1.z = (o6 - mu) * r * ga1.z + be1.z;
        r1.w = (o7 - mu) * r * ga1.w + be1.w;
        float4* op = (float4*)(out + node * 64 + gl * 8);
        op[0] = r0;
        op[1] = r1;
    }
}

// ---------------------------------------------------------------------------
extern "C" void kernel_launch(void* const* d_in, const int* in_sizes, int n_in,
                              void* d_out, int out_size) {
    const float* x     = (const float*)d_in[0];
    const void*  ei    = d_in[1];
    const float* W     = (const float*)d_in[2];
    const float* att_s = (const float*)d_in[3];
    const float* att_d = (const float*)d_in[4];
    const float* bias  = (const float*)d_in[5];
    const float* gamma = (const float*)d_in[6];
    const float* beta  = (const float*)d_in[7];
    float* out = (float*)d_out;

    int n = in_sizes[0] / DIM;    // 100000
    int e = in_sizes[1] / 2;      // 1000000
    int nbs = (n + 1023) / 1024;  // 98 scan blocks (<=128)

    // one-time resource init (streams/events; no device memory)
    static cudaStream_t s2 = 0;
    static cudaEvent_t evF = 0, evJ = 0;
    if (s2 == 0) {
        cudaStreamCreateWithFlags(&s2, cudaStreamNonBlocking);
        cudaEventCreateWithFlags(&evF, cudaEventDisableTiming);
        cudaEventCreateWithFlags(&evJ, cudaEventDisableTiming);
    }

    // main: zero/detect, then edge pipeline; side stream: gemm (independent).
    k_zero_detect<<<(n + 255) / 256, 256>>>((const unsigned*)ei, n, e);
    cudaEventRecord(evF, 0);
    cudaStreamWaitEvent(s2, evF, 0);
    k_gemm<<<(n + 255) / 256, 256, 0, s2>>>(x, W, att_s, att_d, n);
    cudaEventRecord(evJ, s2);

    k_count<<<(e / 2 + 255) / 256, 256>>>(ei, e, n);
    k_scan<<<nbs, 256>>>(n);
    k_scatter<<<(e / 2 + 255) / 256, 256>>>(ei, e, n);

    cudaStreamWaitEvent(0, evJ, 0);
    k_node<<<(n + 31) / 32, 256>>>(bias, gamma, beta, out, n);
}

// round 15
// speedup vs baseline: 1.0580x; 1.0205x over previous
#include <cuda_runtime.h>
#include <cuda_fp16.h>

#define HEADS 4
#define DIM 64
#define NEG_SLOPE 0.2f
#define NODES_MAX 100000
#define EDGES_MAX 1000000

// ---- scratch (static __device__; no allocation) ----
__device__ __half2 g_h[NODES_MAX * 32];      // 12.8 MB, L2-resident (fp16)
__device__ float4 g_asrc[NODES_MAX];
__device__ float4 g_adst[NODES_MAX];
__device__ int    g_counts[NODES_MAX];
__device__ int    g_offsets[NODES_MAX + 1];
__device__ int    g_rank[EDGES_MAX];         // edge's rank within its dst segment
__device__ int    g_scan_tot[128];
__device__ int    g_scan_flag[128];
__device__ int    g_srcs[EDGES_MAX];
__device__ int    g_is64;

__device__ __forceinline__ void ffma2(unsigned long long& d, unsigned long long a,
                                      unsigned long long b) {
    asm("fma.rn.f32x2 %0, %1, %2, %0;" : "+l"(d) : "l"(a), "l"(b));
}

__device__ __forceinline__ int clampi(long long v, int n) {
    int x = (int)v;
    return x < 0 ? 0 : (x >= n ? n - 1 : x);
}

// ---------------------------------------------------------------------------
// zero counts + scan flags + sentinel offset + detect edge_index dtype
__global__ void k_zero_detect(const unsigned* __restrict__ ei, int n, int e) {
    int i = blockIdx.x * blockDim.x + threadIdx.x;
    if (i < n) g_counts[i] = 0;
    if (i < 128) g_scan_flag[i] = 0;
    if (i == 0) g_offsets[n] = e;
    if (blockIdx.x == 0 && threadIdx.x < 32) {
        unsigned lane = threadIdx.x;
        unsigned v1 = ei[2u * lane + 1u];
        unsigned v2 = ei[2u * (lane + 32u) + 1u];
        int nz = (v1 != 0u) || (v2 != 0u);
        unsigned any = __ballot_sync(0xffffffffu, nz);
        if (lane == 0) g_is64 = (any == 0u) ? 1 : 0;
    }
}

// ---------------------------------------------------------------------------
// h = x @ W + attention scalars (side stream, overlapped with edge pipeline).
__global__ void __launch_bounds__(256) k_gemm(
        const float* __restrict__ x, const float* __restrict__ W,
        const float* __restrict__ att_s, const float* __restrict__ att_d, int n) {
    __shared__ unsigned long long sx[8][4 * 64];
    int tid = threadIdx.x, lane = tid & 31, wid = tid >> 5;
    int rowBase = (blockIdx.x * 8 + wid) * 32;

    unsigned long long Wr[64];
    #pragma unroll
    for (int k = 0; k < 64; k++)
        Wr[k] = *(const unsigned long long*)(W + k * 64 + lane * 2);
    float2 asw = *(const float2*)(att_s + lane * 2);
    float2 adw = *(const float2*)(att_d + lane * 2);

    unsigned FULL = 0xffffffffu;
    int hdsel = lane >> 3;

    for (int r4 = 0; r4 < 32; r4 += 4) {
        int row0 = rowBase + r4;

        #pragma unroll
        for (int it = 0; it < 4; it++) {
            int g2 = it * 32 + lane;
            int r = g2 >> 5;
            float2 v = make_float2(0.f, 0.f);
            if (row0 + r < n) v = ((const float2*)x)[row0 * 32 + g2];
            sx[wid][g2 * 2]     = ((unsigned long long)__float_as_uint(v.x) << 32) |
                                   (unsigned long long)__float_as_uint(v.x);
            sx[wid][g2 * 2 + 1] = ((unsigned long long)__float_as_uint(v.y) << 32) |
                                   (unsigned long long)__float_as_uint(v.y);
        }
        __syncwarp();

        unsigned long long a0 = 0ull, a1 = 0ull, a2 = 0ull, a3 = 0ull;
        const unsigned long long* xr = &sx[wid][0];
        #pragma unroll
        for (int k = 0; k < 64; k++) {
            ffma2(a0, xr[k],       Wr[k]);
            ffma2(a1, xr[64 + k],  Wr[k]);
            ffma2(a2, xr[128 + k], Wr[k]);
            ffma2(a3, xr[192 + k], Wr[k]);
        }
        __syncwarp();

        unsigned long long accs[4] = {a0, a1, a2, a3};
        #pragma unroll
        for (int r = 0; r < 4; r++) {
            int row = row0 + r;
            float c0 = __uint_as_float((unsigned)(accs[r] & 0xffffffffull));
            float c1 = __uint_as_float((unsigned)(accs[r] >> 32));
            if (row < n)
                g_h[row * 32 + lane] = __floats2half2_rn(c0, c1);
            float ts = c0 * asw.x + c1 * asw.y;
            float td = c0 * adw.x + c1 * adw.y;
            #pragma unroll
            for (int m = 1; m < 8; m <<= 1) {
                ts += __shfl_xor_sync(FULL, ts, m);
                td += __shfl_xor_sync(FULL, td, m);
            }
            if (row < n && (lane & 7) == 0) {
                ((float*)g_asrc)[row * 4 + hdsel] = ts;
                ((float*)g_adst)[row * 4 + hdsel] = td;
            }
        }
    }
}

// ---------------------------------------------------------------------------
// in-degree histogram; atomic return value = edge rank in its dst segment.
__global__ void k_count(const void* __restrict__ ei, int e, int n) {
    int i0 = (blockIdx.x * blockDim.x + threadIdx.x) * 2;
    if (i0 >= e) return;
    int is64 = g_is64;
    if (i0 + 2 <= e) {
        int d0, d1;
        if (is64) {
            longlong2 d = *(const longlong2*)((const long long*)ei + e + i0);
            d0 = clampi(d.x, n); d1 = clampi(d.y, n);
        } else {
            int2 d = *(const int2*)((const int*)ei + e + i0);
            d0 = clampi(d.x, n); d1 = clampi(d.y, n);
        }
        int r0 = atomicAdd(&g_counts[d0], 1);
        int r1 = atomicAdd(&g_counts[d1], 1);
        *(int2*)(g_rank + i0) = make_int2(r0, r1);
    } else {
        long long d = is64 ? ((const long long*)ei)[e + i0]
                           : (long long)((const int*)ei)[e + i0];
        g_rank[i0] = atomicAdd(&g_counts[clampi(d, n)], 1);
    }
}

// ---------------------------------------------------------------------------
// exclusive scan: 98 blocks x 256 threads x 4 elems; warp-shuffle scan
// + decoupled predecessor-only lookback (concurrency-safe).
__global__ void __launch_bounds__(256) k_scan(int n) {
    __shared__ int wtot[8];
    __shared__ int s_pref;
    int t = threadIdx.x, b = blockIdx.x;
    int lane = t & 31, wid = t >> 5;
    unsigned FULL = 0xffffffffu;

    int base = (b * 256 + t) * 4;
    int4 v = make_int4(0, 0, 0, 0);
    if (base + 4 <= n) v = *(const int4*)(g_counts + base);
    else {
        if (base < n)     v.x = g_counts[base];
        if (base + 1 < n) v.y = g_counts[base + 1];
        if (base + 2 < n) v.z = g_counts[base + 2];
    }
    int local = v.x + v.y + v.z + v.w;

    int ws = local;
    #pragma unroll
    for (int o = 1; o < 32; o <<= 1) {
        int u = __shfl_up_sync(FULL, ws, o);
        if (lane >= o) ws += u;
    }
    if (lane == 31) wtot[wid] = ws;
    __syncthreads();

    if (t < 32) {
        int w = (t < 8) ? wtot[t] : 0;
        #pragma unroll
        for (int o = 1; o < 8; o <<= 1) {
            int u = __shfl_up_sync(FULL, w, o);
            if (t >= o) w += u;
        }
        if (t < 8) wtot[t] = w;
        int btot = __shfl_sync(FULL, w, 7);
        if (t == 0) {
            g_scan_tot[b] = btot;
            __threadfence();
            atomicExch(&g_scan_flag[b], 1);
        }
        int acc = 0;
        for (int i = t; i < b; i += 32) {
            while (((volatile int*)g_scan_flag)[i] == 0) { }
            acc += ((volatile int*)g_scan_tot)[i];
        }
        #pragma unroll
        for (int o = 16; o; o >>= 1) acc += __shfl_xor_sync(FULL, acc, o);
        if (t == 0) s_pref = acc;
    }
    __syncthreads();

    int blkpre = wid ? wtot[wid - 1] : 0;
    int pref = s_pref + blkpre + ws - local;
    int o0 = pref, o1 = o0 + v.x, o2 = o1 + v.y, o3 = o2 + v.z;
    if (base + 4 <= n) {
        *(int4*)(g_offsets + base) = make_int4(o0, o1, o2, o3);
    } else {
        int ov[4] = {o0, o1, o2, o3};
        for (int i = 0; base + i < n && i < 4; i++)
            g_offsets[base + i] = ov[i];
    }
}

// ---------------------------------------------------------------------------
// atomic-free scatter: pos = offsets[dst] + precomputed rank.
__global__ void k_scatter(const void* __restrict__ ei, int e, int n) {
    int i0 = (blockIdx.x * blockDim.x + threadIdx.x) * 2;
    if (i0 >= e) return;
    int is64 = g_is64;
    if (i0 + 2 <= e) {
        int s0, s1, d0, d1;
        if (is64) {
            longlong2 s = *(const longlong2*)((const long long*)ei + i0);
            longlong2 d = *(const longlong2*)((const long long*)ei + e + i0);
            s0 = clampi(s.x, n); s1 = clampi(s.y, n);
            d0 = clampi(d.x, n); d1 = clampi(d.y, n);
        } else {
            int2 s = *(const int2*)((const int*)ei + i0);
            int2 d = *(const int2*)((const int*)ei + e + i0);
            s0 = clampi(s.x, n); s1 = clampi(s.y, n);
            d0 = clampi(d.x, n); d1 = clampi(d.y, n);
        }
        int2 rk = *(const int2*)(g_rank + i0);
        int p0 = g_offsets[d0] + rk.x;
        int p1 = g_offsets[d1] + rk.y;
        g_srcs[p0] = s0;
        g_srcs[p1] = s1;
    } else {
        long long sl = is64 ? ((const long long*)ei)[i0]
                            : (long long)((const int*)ei)[i0];
        long long dl = is64 ? ((const long long*)ei)[e + i0]
                            : (long long)((const int*)ei)[e + i0];
        int pos = g_offsets[clampi(dl, n)] + g_rank[i0];
        g_srcs[pos] = clampi(sl, n);
    }
}

// ---------------------------------------------------------------------------
// 4 nodes per warp (8-lane groups). Lane owns 8 channels (LDG.128 fp16).
// Transposed smem (head-major) -> inner loop reads alphas/srcs with 2+2
// LDS.128 into registers; gather loop fully unrolled on register operands.
__global__ void __launch_bounds__(256) k_node(
        const float* __restrict__ bias, const float* __restrict__ gamma,
        const float* __restrict__ beta, float* __restrict__ out, int n) {
    __shared__ float s_exT[8][4][4][8];   // [warp][head][group][edge]
    __shared__ int   s_src[8][4][8];      // [warp][group][edge]
    int wslot = threadIdx.x >> 5, lane = threadIdx.x & 31;
    int grp = lane >> 3, gl = lane & 7;
    int node = (blockIdx.x * 8 + wslot) * 4 + grp;
    bool valid = node < n;
    unsigned FULL = 0xffffffffu;

    int beg = 0, deg = 0;
    float4 ad = make_float4(0.f, 0.f, 0.f, 0.f);
    if (valid) {
        beg = g_offsets[node];
        deg = g_offsets[node + 1] - beg;
        ad = g_adst[node];
    }
    int hd = gl >> 1;

    float s0 = 0.f, s1 = 0.f, s2 = 0.f, s3 = 0.f;
    float a0 = 0.f, a1 = 0.f, a2 = 0.f, a3 = 0.f;
    float a4 = 0.f, a5 = 0.f, a6 = 0.f, a7 = 0.f;

    const uint4* hb = (const uint4*)g_h;

    int nch = (deg + 7) >> 3;
    #pragma unroll
    for (int o = 16; o; o >>= 1) nch = max(nch, __shfl_xor_sync(FULL, nch, o));

    for (int c = 0; c < nch; c++) {
        int i = c * 8 + gl;
        float4 ex4 = make_float4(0.f, 0.f, 0.f, 0.f);
        int sv = 0;
        if (i < deg) {
            sv = g_srcs[beg + i];
            float4 as = g_asrc[sv];
            float e0 = as.x + ad.x; e0 = e0 >= 0.f ? e0 : NEG_SLOPE * e0;
            float e1 = as.y + ad.y; e1 = e1 >= 0.f ? e1 : NEG_SLOPE * e1;
            float e2 = as.z + ad.z; e2 = e2 >= 0.f ? e2 : NEG_SLOPE * e2;
            float e3 = as.w + ad.w; e3 = e3 >= 0.f ? e3 : NEG_SLOPE * e3;
            ex4.x = __expf(e0); ex4.y = __expf(e1);
            ex4.z = __expf(e2); ex4.w = __expf(e3);
            s0 += ex4.x; s1 += ex4.y; s2 += ex4.z; s3 += ex4.w;
        }
        s_src[wslot][grp][gl] = sv;
        s_exT[wslot][0][grp][gl] = ex4.x;   // bank = grp*8+gl = lane: conflict-free
        s_exT[wslot][1][grp][gl] = ex4.y;
        s_exT[wslot][2][grp][gl] = ex4.z;
        s_exT[wslot][3][grp][gl] = ex4.w;
        __syncwarp();

        // register-resident operands: 2+2 LDS.128
        int4   sA = *(const int4*)&s_src[wslot][grp][0];
        int4   sB = *(const int4*)&s_src[wslot][grp][4];
        float4 aA = *(const float4*)&s_exT[wslot][hd][grp][0];
        float4 aB = *(const float4*)&s_exT[wslot][hd][grp][4];
        int cnt = min(8, deg - c * 8);

        #pragma unroll
        for (int j = 0; j < 8; j++) {
            int   ss = (j < 4) ? ((const int*)&sA)[j]     : ((const int*)&sB)[j - 4];
            float al = (j < 4) ? ((const float*)&aA)[j]   : ((const float*)&aB)[j - 4];
            if (j < cnt) {
                uint4 hv = hb[ss * 8 + gl];
                float2 p0 = __half22float2(*(__half2*)&hv.x);
                float2 p1 = __half22float2(*(__half2*)&hv.y);
                float2 p2 = __half22float2(*(__half2*)&hv.z);
                float2 p3 = __half22float2(*(__half2*)&hv.w);
                a0 = fmaf(al, p0.x, a0); a1 = fmaf(al, p0.y, a1);
                a2 = fmaf(al, p1.x, a2); a3 = fmaf(al, p1.y, a3);
                a4 = fmaf(al, p2.x, a4); a5 = fmaf(al, p2.y, a5);
                a6 = fmaf(al, p3.x, a6); a7 = fmaf(al, p3.y, a7);
            }
        }
        __syncwarp();
    }

    #pragma unroll
    for (int o = 4; o; o >>= 1) {
        s0 += __shfl_xor_sync(FULL, s0, o);
        s1 += __shfl_xor_sync(FULL, s1, o);
        s2 += __shfl_xor_sync(FULL, s2, o);
        s3 += __shfl_xor_sync(FULL, s3, o);
    }
    float s   = (hd == 0) ? s0 : (hd == 1) ? s1 : (hd == 2) ? s2 : s3;
    float inv = 1.f / (s + 1e-16f);

    float4 bi0 = *(const float4*)(bias + gl * 8);
    float4 bi1 = *(const float4*)(bias + gl * 8 + 4);
    float o0 = a0 * inv + bi0.x, o1 = a1 * inv + bi0.y;
    float o2 = a2 * inv + bi0.z, o3 = a3 * inv + bi0.w;
    float o4 = a4 * inv + bi1.x, o5 = a5 * inv + bi1.y;
    float o6 = a6 * inv + bi1.z, o7 = a7 * inv + bi1.w;

    float ssum = o0 + o1 + o2 + o3 + o4 + o5 + o6 + o7;
    float ssq  = o0*o0 + o1*o1 + o2*o2 + o3*o3 + o4*o4 + o5*o5 + o6*o6 + o7*o7;
    #pragma unroll
    for (int o = 4; o; o >>= 1) {
        ssum += __shfl_xor_sync(FULL, ssum, o);
        ssq  += __shfl_xor_sync(FULL, ssq, o);
    }
    float mu  = ssum * (1.f / 64.f);
    float var = ssq * (1.f / 64.f) - mu * mu;
    float r   = rsqrtf(var + 1e-5f);

    if (valid) {
        float4 ga0 = *(const float4*)(gamma + gl * 8);
        float4 ga1 = *(const float4*)(gamma + gl * 8 + 4);
        float4 be0 = *(const float4*)(beta + gl * 8);
        float4 be1 = *(const float4*)(beta + gl * 8 + 4);
        float4 r0, r1;
        r0.x = (o0 - mu) * r * ga0.x + be0.x;
        r0.y = (o1 - mu) * r * ga0.y + be0.y;
        r0.z = (o2 - mu) * r * ga0.z + be0.z;
        r0.w = (o3 - mu) * r * ga0.w + be0.w;
        r1.x = (o4 - mu) * r * ga1.x + be1.x;
        r1.y = (o5 - mu) * r * ga1.y + be1.y;
        r1.z = (o6 - mu) * r * ga1.z + be1.z;
        r1.w = (o7 - mu) * r * ga1.w + be1.w;
        float4* op = (float4*)(out + node * 64 + gl * 8);
        op[0] = r0;
        op[1] = r1;
    }
}

// ---------------------------------------------------------------------------
extern "C" void kernel_launch(void* const* d_in, const int* in_sizes, int n_in,
                              void* d_out, int out_size) {
    const float* x     = (const float*)d_in[0];
    const void*  ei    = d_in[1];
    const float* W     = (const float*)d_in[2];
    const float* att_s = (const float*)d_in[3];
    const float* att_d = (const float*)d_in[4];
    const float* bias  = (const float*)d_in[5];
    const float* gamma = (const float*)d_in[6];
    const float* beta  = (const float*)d_in[7];
    float* out = (float*)d_out;

    int n = in_sizes[0] / DIM;    // 100000
    int e = in_sizes[1] / 2;      // 1000000
    int nbs = (n + 1023) / 1024;  // 98 scan blocks (<=128)

    // one-time resource init (streams/events; no device memory)
    static cudaStream_t s2 = 0;
    static cudaEvent_t evF = 0, evJ = 0;
    if (s2 == 0) {
        cudaStreamCreateWithFlags(&s2, cudaStreamNonBlocking);
        cudaEventCreateWithFlags(&evF, cudaEventDisableTiming);
        cudaEventCreateWithFlags(&evJ, cudaEventDisableTiming);
    }

    // main: zero/detect, then edge pipeline; side stream: gemm (independent).
    k_zero_detect<<<(n + 255) / 256, 256>>>((const unsigned*)ei, n, e);
    cudaEventRecord(evF, 0);
    cudaStreamWaitEvent(s2, evF, 0);
    k_gemm<<<(n + 255) / 256, 256, 0, s2>>>(x, W, att_s, att_d, n);
    cudaEventRecord(evJ, s2);

    k_count<<<(e / 2 + 255) / 256, 256>>>(ei, e, n);
    k_scan<<<nbs, 256>>>(n);
    k_scatter<<<(e / 2 + 255) / 256, 256>>>(ei, e, n);

    cudaStreamWaitEvent(0, evJ, 0);
    k_node<<<(n + 31) / 32, 256>>>(bias, gamma, beta, out, n);
}

// round 16
// speedup vs baseline: 1.0603x; 1.0022x over previous
#include <cuda_runtime.h>
#include <cuda_fp16.h>

#define HEADS 4
#define DIM 64
#define NEG_SLOPE 0.2f
#define NODES_MAX 100000
#define EDGES_MAX 1000000

// ---- scratch (static __device__; no allocation) ----
__device__ __half2 g_h[NODES_MAX * 32];      // 12.8 MB, L2-resident (fp16)
__device__ float4 g_asrc[NODES_MAX];
__device__ float4 g_adst[NODES_MAX];
__device__ int    g_counts[NODES_MAX];       // BSS-zero; re-zeroed by k_scatter each run
__device__ int    g_offsets[NODES_MAX + 1];
__device__ int    g_rank[EDGES_MAX];         // edge's rank within its dst segment
__device__ int    g_scan_tot[128];
__device__ int    g_scan_flag[128];
__device__ int    g_fin;                     // count-completion counter
__device__ int    g_srcs[EDGES_MAX];
__device__ int    g_is64;

__device__ __forceinline__ void ffma2(unsigned long long& d, unsigned long long a,
                                      unsigned long long b) {
    asm("fma.rn.f32x2 %0, %1, %2, %0;" : "+l"(d) : "l"(a), "l"(b));
}

__device__ __forceinline__ int clampi(long long v, int n) {
    int x = (int)v;
    return x < 0 ? 0 : (x >= n ? n - 1 : x);
}

// ---------------------------------------------------------------------------
// 1-block init: scan flags + fin + sentinel + dtype detect (counts zeroing
// lives in k_scatter; g_counts is BSS-zero on first run).
__global__ void k_init(const unsigned* __restrict__ ei, int n, int e) {
    int t = threadIdx.x;
    g_scan_flag[t] = 0;
    if (t == 0) { g_offsets[n] = e; g_fin = 0; }
    if (t < 32) {
        unsigned v1 = ei[2u * t + 1u];
        unsigned v2 = ei[2u * (t + 32u) + 1u];
        int nz = (v1 != 0u) || (v2 != 0u);
        unsigned any = __ballot_sync(0xffffffffu, nz);
        if (t == 0) g_is64 = (any == 0u) ? 1 : 0;
    }
}

// ---------------------------------------------------------------------------
// h = x @ W + attention scalars (side stream, overlapped with edge pipeline).
__global__ void __launch_bounds__(256) k_gemm(
        const float* __restrict__ x, const float* __restrict__ W,
        const float* __restrict__ att_s, const float* __restrict__ att_d, int n) {
    __shared__ unsigned long long sx[8][4 * 64];
    int tid = threadIdx.x, lane = tid & 31, wid = tid >> 5;
    int rowBase = (blockIdx.x * 8 + wid) * 32;

    unsigned long long Wr[64];
    #pragma unroll
    for (int k = 0; k < 64; k++)
        Wr[k] = *(const unsigned long long*)(W + k * 64 + lane * 2);
    float2 asw = *(const float2*)(att_s + lane * 2);
    float2 adw = *(const float2*)(att_d + lane * 2);

    unsigned FULL = 0xffffffffu;
    int hdsel = lane >> 3;

    for (int r4 = 0; r4 < 32; r4 += 4) {
        int row0 = rowBase + r4;

        #pragma unroll
        for (int it = 0; it < 4; it++) {
            int g2 = it * 32 + lane;
            int r = g2 >> 5;
            float2 v = make_float2(0.f, 0.f);
            if (row0 + r < n) v = ((const float2*)x)[row0 * 32 + g2];
            sx[wid][g2 * 2]     = ((unsigned long long)__float_as_uint(v.x) << 32) |
                                   (unsigned long long)__float_as_uint(v.x);
            sx[wid][g2 * 2 + 1] = ((unsigned long long)__float_as_uint(v.y) << 32) |
                                   (unsigned long long)__float_as_uint(v.y);
        }
        __syncwarp();

        unsigned long long a0 = 0ull, a1 = 0ull, a2 = 0ull, a3 = 0ull;
        const unsigned long long* xr = &sx[wid][0];
        #pragma unroll
        for (int k = 0; k < 64; k++) {
            ffma2(a0, xr[k],       Wr[k]);
            ffma2(a1, xr[64 + k],  Wr[k]);
            ffma2(a2, xr[128 + k], Wr[k]);
            ffma2(a3, xr[192 + k], Wr[k]);
        }
        __syncwarp();

        unsigned long long accs[4] = {a0, a1, a2, a3};
        #pragma unroll
        for (int r = 0; r < 4; r++) {
            int row = row0 + r;
            float c0 = __uint_as_float((unsigned)(accs[r] & 0xffffffffull));
            float c1 = __uint_as_float((unsigned)(accs[r] >> 32));
            if (row < n)
                g_h[row * 32 + lane] = __floats2half2_rn(c0, c1);
            float ts = c0 * asw.x + c1 * asw.y;
            float td = c0 * adw.x + c1 * adw.y;
            #pragma unroll
            for (int m = 1; m < 8; m <<= 1) {
                ts += __shfl_xor_sync(FULL, ts, m);
                td += __shfl_xor_sync(FULL, td, m);
            }
            if (row < n && (lane & 7) == 0) {
                ((float*)g_asrc)[row * 4 + hdsel] = ts;
                ((float*)g_adst)[row * 4 + hdsel] = td;
            }
        }
    }
}

// ---------------------------------------------------------------------------
// FUSED count + scan.
// All blocks: histogram (atomic return = rank), then bump g_fin.
// Blocks 0..nsb-1 ONLY (first-dispatched -> wave-1 resident; <10% of slots):
// spin until g_fin==gridDim.x, then exclusive scan (warp shuffles +
// predecessor-only lookback). Spinners never block later count blocks.
__global__ void __launch_bounds__(256) k_countscan(const void* __restrict__ ei,
                                                   int e, int n, int nsb) {
    int t = threadIdx.x, b = blockIdx.x;
    unsigned FULL = 0xffffffffu;
    int is64 = g_is64;

    // ---- count phase ----
    int i0 = (b * 256 + t) * 2;
    if (i0 < e) {
        if (i0 + 2 <= e) {
            int d0, d1;
            if (is64) {
                longlong2 d = *(const longlong2*)((const long long*)ei + e + i0);
                d0 = clampi(d.x, n); d1 = clampi(d.y, n);
            } else {
                int2 d = *(const int2*)((const int*)ei + e + i0);
                d0 = clampi(d.x, n); d1 = clampi(d.y, n);
            }
            int r0 = atomicAdd(&g_counts[d0], 1);
            int r1 = atomicAdd(&g_counts[d1], 1);
            *(int2*)(g_rank + i0) = make_int2(r0, r1);
        } else {
            long long d = is64 ? ((const long long*)ei)[e + i0]
                               : (long long)((const int*)ei)[e + i0];
            g_rank[i0] = atomicAdd(&g_counts[clampi(d, n)], 1);
        }
    }
    __threadfence();
    __syncthreads();
    if (t == 0) atomicAdd(&g_fin, 1);

    if (b >= nsb) return;

    // ---- scan phase (blocks 0..nsb-1) ----
    if (t == 0) {
        while (*(volatile int*)&g_fin < (int)gridDim.x) { __nanosleep(64); }
    }
    __syncthreads();
    __threadfence();

    __shared__ int wtot[8];
    __shared__ int s_pref;
    int lane = t & 31, wid = t >> 5;

    int base = (b * 256 + t) * 4;
    int4 v = make_int4(0, 0, 0, 0);
    if (base + 4 <= n) v = *(const int4*)(g_counts + base);
    else {
        if (base < n)     v.x = g_counts[base];
        if (base + 1 < n) v.y = g_counts[base + 1];
        if (base + 2 < n) v.z = g_counts[base + 2];
    }
    int local = v.x + v.y + v.z + v.w;

    int ws = local;
    #pragma unroll
    for (int o = 1; o < 32; o <<= 1) {
        int u = __shfl_up_sync(FULL, ws, o);
        if (lane >= o) ws += u;
    }
    if (lane == 31) wtot[wid] = ws;
    __syncthreads();

    if (t < 32) {
        int w = (t < 8) ? wtot[t] : 0;
        #pragma unroll
        for (int o = 1; o < 8; o <<= 1) {
            int u = __shfl_up_sync(FULL, w, o);
            if (t >= o) w += u;
        }
        if (t < 8) wtot[t] = w;
        int btot = __shfl_sync(FULL, w, 7);
        if (t == 0) {
            g_scan_tot[b] = btot;
            __threadfence();
            atomicExch(&g_scan_flag[b], 1);
        }
        int acc = 0;
        for (int i = t; i < b; i += 32) {
            while (((volatile int*)g_scan_flag)[i] == 0) { }
            acc += ((volatile int*)g_scan_tot)[i];
        }
        #pragma unroll
        for (int o = 16; o; o >>= 1) acc += __shfl_xor_sync(FULL, acc, o);
        if (t == 0) s_pref = acc;
    }
    __syncthreads();

    int blkpre = wid ? wtot[wid - 1] : 0;
    int pref = s_pref + blkpre + ws - local;   // exclusive prefix
    int o0 = pref, o1 = o0 + v.x, o2 = o1 + v.y, o3 = o2 + v.z;
    if (base + 4 <= n) {
        *(int4*)(g_offsets + base) = make_int4(o0, o1, o2, o3);
    } else {
        int ov[4] = {o0, o1, o2, o3};
        for (int i = 0; base + i < n && i < 4; i++)
            g_offsets[base + i] = ov[i];
    }
}

// ---------------------------------------------------------------------------
// atomic-free scatter: pos = offsets[dst] + precomputed rank.
// Also re-zeroes g_counts (consumed by scan; restores state for next run).
__global__ void k_scatter(const void* __restrict__ ei, int e, int n) {
    int gtid = blockIdx.x * blockDim.x + threadIdx.x;
    if (gtid < n) g_counts[gtid] = 0;      // 500K threads >= n

    int i0 = gtid * 2;
    if (i0 >= e) return;
    int is64 = g_is64;
    if (i0 + 2 <= e) {
        int s0, s1, d0, d1;
        if (is64) {
            longlong2 s = *(const longlong2*)((const long long*)ei + i0);
            longlong2 d = *(const longlong2*)((const long long*)ei + e + i0);
            s0 = clampi(s.x, n); s1 = clampi(s.y, n);
            d0 = clampi(d.x, n); d1 = clampi(d.y, n);
        } else {
            int2 s = *(const int2*)((const int*)ei + i0);
            int2 d = *(const int2*)((const int*)ei + e + i0);
            s0 = clampi(s.x, n); s1 = clampi(s.y, n);
            d0 = clampi(d.x, n); d1 = clampi(d.y, n);
        }
        int2 rk = *(const int2*)(g_rank + i0);
        int p0 = g_offsets[d0] + rk.x;
        int p1 = g_offsets[d1] + rk.y;
        g_srcs[p0] = s0;
        g_srcs[p1] = s1;
    } else {
        long long sl = is64 ? ((const long long*)ei)[i0]
                            : (long long)((const int*)ei)[i0];
        long long dl = is64 ? ((const long long*)ei)[e + i0]
                            : (long long)((const int*)ei)[e + i0];
        int pos = g_offsets[clampi(dl, n)] + g_rank[i0];
        g_srcs[pos] = clampi(sl, n);
    }
}

// ---------------------------------------------------------------------------
// 4 nodes per warp (8-lane groups). Lane owns 8 channels (LDG.128 fp16).
// Transposed smem (head-major) -> register-resident alphas/srcs per chunk.
__global__ void __launch_bounds__(256) k_node(
        const float* __restrict__ bias, const float* __restrict__ gamma,
        const float* __restrict__ beta, float* __restrict__ out, int n) {
    __shared__ float s_exT[8][4][4][8];   // [warp][head][group][edge]
    __shared__ int   s_src[8][4][8];      // [warp][group][edge]
    int wslot = threadIdx.x >> 5, lane = threadIdx.x & 31;
    int grp = lane >> 3, gl = lane & 7;
    int node = (blockIdx.x * 8 + wslot) * 4 + grp;
    bool valid = node < n;
    unsigned FULL = 0xffffffffu;

    int beg = 0, deg = 0;
    float4 ad = make_float4(0.f, 0.f, 0.f, 0.f);
    if (valid) {
        beg = g_offsets[node];
        deg = g_offsets[node + 1] - beg;
        ad = g_adst[node];
    }
    int hd = gl >> 1;

    float s0 = 0.f, s1 = 0.f, s2 = 0.f, s3 = 0.f;
    float a0 = 0.f, a1 = 0.f, a2 = 0.f, a3 = 0.f;
    float a4 = 0.f, a5 = 0.f, a6 = 0.f, a7 = 0.f;

    const uint4* hb = (const uint4*)g_h;

    int nch = (deg + 7) >> 3;
    #pragma unroll
    for (int o = 16; o; o >>= 1) nch = max(nch, __shfl_xor_sync(FULL, nch, o));

    for (int c = 0; c < nch; c++) {
        int i = c * 8 + gl;
        float4 ex4 = make_float4(0.f, 0.f, 0.f, 0.f);
        int sv = 0;
        if (i < deg) {
            sv = g_srcs[beg + i];
            float4 as = g_asrc[sv];
            float e0 = as.x + ad.x; e0 = e0 >= 0.f ? e0 : NEG_SLOPE * e0;
            float e1 = as.y + ad.y; e1 = e1 >= 0.f ? e1 : NEG_SLOPE * e1;
            float e2 = as.z + ad.z; e2 = e2 >= 0.f ? e2 : NEG_SLOPE * e2;
            float e3 = as.w + ad.w; e3 = e3 >= 0.f ? e3 : NEG_SLOPE * e3;
            ex4.x = __expf(e0); ex4.y = __expf(e1);
            ex4.z = __expf(e2); ex4.w = __expf(e3);
            s0 += ex4.x; s1 += ex4.y; s2 += ex4.z; s3 += ex4.w;
        }
        s_src[wslot][grp][gl] = sv;
        s_exT[wslot][0][grp][gl] = ex4.x;   // bank = grp*8+gl = lane: conflict-free
        s_exT[wslot][1][grp][gl] = ex4.y;
        s_exT[wslot][2][grp][gl] = ex4.z;
        s_exT[wslot][3][grp][gl] = ex4.w;
        __syncwarp();

        int4   sA = *(const int4*)&s_src[wslot][grp][0];
        int4   sB = *(const int4*)&s_src[wslot][grp][4];
        float4 aA = *(const float4*)&s_exT[wslot][hd][grp][0];
        float4 aB = *(const float4*)&s_exT[wslot][hd][grp][4];
        int cnt = min(8, deg - c * 8);

        #pragma unroll
        for (int j = 0; j < 8; j++) {
            int   ss = (j < 4) ? ((const int*)&sA)[j]   : ((const int*)&sB)[j - 4];
            float al = (j < 4) ? ((const float*)&aA)[j] : ((const float*)&aB)[j - 4];
            if (j < cnt) {
                uint4 hv = hb[ss * 8 + gl];
                float2 p0 = __half22float2(*(__half2*)&hv.x);
                float2 p1 = __half22float2(*(__half2*)&hv.y);
                float2 p2 = __half22float2(*(__half2*)&hv.z);
                float2 p3 = __half22float2(*(__half2*)&hv.w);
                a0 = fmaf(al, p0.x, a0); a1 = fmaf(al, p0.y, a1);
                a2 = fmaf(al, p1.x, a2); a3 = fmaf(al, p1.y, a3);
                a4 = fmaf(al, p2.x, a4); a5 = fmaf(al, p2.y, a5);
                a6 = fmaf(al, p3.x, a6); a7 = fmaf(al, p3.y, a7);
            }
        }
        __syncwarp();
    }

    #pragma unroll
    for (int o = 4; o; o >>= 1) {
        s0 += __shfl_xor_sync(FULL, s0, o);
        s1 += __shfl_xor_sync(FULL, s1, o);
        s2 += __shfl_xor_sync(FULL, s2, o);
        s3 += __shfl_xor_sync(FULL, s3, o);
    }
    float s   = (hd == 0) ? s0 : (hd == 1) ? s1 : (hd == 2) ? s2 : s3;
    float inv = 1.f / (s + 1e-16f);

    float4 bi0 = *(const float4*)(bias + gl * 8);
    float4 bi1 = *(const float4*)(bias + gl * 8 + 4);
    float o0 = a0 * inv + bi0.x, o1 = a1 * inv + bi0.y;
    float o2 = a2 * inv + bi0.z, o3 = a3 * inv + bi0.w;
    float o4 = a4 * inv + bi1.x, o5 = a5 * inv + bi1.y;
    float o6 = a6 * inv + bi1.z, o7 = a7 * inv + bi1.w;

    float ssum = o0 + o1 + o2 + o3 + o4 + o5 + o6 + o7;
    float ssq  = o0*o0 + o1*o1 + o2*o2 + o3*o3 + o4*o4 + o5*o5 + o6*o6 + o7*o7;
    #pragma unroll
    for (int o = 4; o; o >>= 1) {
        ssum += __shfl_xor_sync(FULL, ssum, o);
        ssq  += __shfl_xor_sync(FULL, ssq, o);
    }
    float mu  = ssum * (1.f / 64.f);
    float var = ssq * (1.f / 64.f) - mu * mu;
    float r   = rsqrtf(var + 1e-5f);

    if (valid) {
        float4 ga0 = *(const float4*)(gamma + gl * 8);
        float4 ga1 = *(const float4*)(gamma + gl * 8 + 4);
        float4 be0 = *(const float4*)(beta + gl * 8);
        float4 be1 = *(const float4*)(beta + gl * 8 + 4);
        float4 r0, r1;
        r0.x = (o0 - mu) * r * ga0.x + be0.x;
        r0.y = (o1 - mu) * r * ga0.y + be0.y;
        r0.z = (o2 - mu) * r * ga0.z + be0.z;
        r0.w = (o3 - mu) * r * ga0.w + be0.w;
        r1.x = (o4 - mu) * r * ga1.x + be1.x;
        r1.y = (o5 - mu) * r * ga1.y + be1.y;
        r1.z = (o6 - mu) * r * ga1.z + be1.z;
        r1.w = (o7 - mu) * r * ga1.w + be1.w;
        float4* op = (float4*)(out + node * 64 + gl * 8);
        op[0] = r0;
        op[1] = r1;
    }
}

// ---------------------------------------------------------------------------
extern "C" void kernel_launch(void* const* d_in, const int* in_sizes, int n_in,
                              void* d_out, int out_size) {
    const float* x     = (const float*)d_in[0];
    const void*  ei    = d_in[1];
    const float* W     = (const float*)d_in[2];
    const float* att_s = (const float*)d_in[3];
    const float* att_d = (const float*)d_in[4];
    const float* bias  = (const float*)d_in[5];
    const float* gamma = (const float*)d_in[6];
    const float* beta  = (const float*)d_in[7];
    float* out = (float*)d_out;

    int n = in_sizes[0] / DIM;    // 100000
    int e = in_sizes[1] / 2;      // 1000000
    int nsb = (n + 1023) / 1024;  // 98 scan blocks (<=128)

    // one-time resource init (streams/events; no device memory)
    static cudaStream_t s2 = 0;
    static cudaEvent_t evF = 0, evJ = 0;
    if (s2 == 0) {
        cudaStreamCreateWithFlags(&s2, cudaStreamNonBlocking);
        cudaEventCreateWithFlags(&evF, cudaEventDisableTiming);
        cudaEventCreateWithFlags(&evJ, cudaEventDisableTiming);
    }

    // main: init, then fused count+scan, scatter; side stream: gemm.
    k_init<<<1, 128>>>((const unsigned*)ei, n, e);
    cudaEventRecord(evF, 0);
    cudaStreamWaitEvent(s2, evF, 0);
    k_gemm<<<(n + 255) / 256, 256, 0, s2>>>(x, W, att_s, att_d, n);
    cudaEventRecord(evJ, s2);

    k_countscan<<<(e / 2 + 255) / 256, 256>>>(ei, e, n, nsb);
    k_scatter<<<(e / 2 + 255) / 256, 256>>>(ei, e, n);

    cudaStreamWaitEvent(0, evJ, 0);
    k_node<<<(n + 31) / 32, 256>>>(bias, gamma, beta, out, n);
}